// round 1
// baseline (speedup 1.0000x reference)
#include <cuda_runtime.h>
#include <mma.h>

using namespace nvcuda;

#define SEQ   2048
#define DIMSZ 4096
#define NHEAD 32
#define HDIM  128

// Scratch (device globals: allocation-free per harness rules)
__device__ float g_q[(size_t)SEQ * DIMSZ];
__device__ float g_k[(size_t)SEQ * DIMSZ];
__device__ float g_v[(size_t)SEQ * DIMSZ];
__device__ float g_o[(size_t)SEQ * DIMSZ];

__device__ __forceinline__ float to_tf32(float x) { return wmma::__float_to_tf32(x); }

// ---------------------------------------------------------------------------
// GEMM: C[M,N] = A[M,K] @ B[K,N], fp32 in/out, TF32 tensor cores.
// Block tile 128x64, BK=32. 256 threads = 8 warps, warp grid 4x2 (32x32 each).
// ---------------------------------------------------------------------------
__global__ __launch_bounds__(256) void gemm_tf32(const float* __restrict__ A,
                                                 const float* __restrict__ B,
                                                 float* __restrict__ C,
                                                 int M, int N, int K)
{
    __shared__ float As[128 * 40];   // 128 rows x 32 k (pad ld=40)
    __shared__ float Bs[32 * 72];    // 32 k x 64 n (pad ld=72)

    const int tid = threadIdx.x;
    const int w   = tid >> 5;
    const int bm  = blockIdx.x * 128;
    const int bn  = blockIdx.y * 64;
    const int wr  = (w >> 1) * 32;   // warp row offset in tile
    const int wc  = (w & 1) * 32;    // warp col offset in tile

    wmma::fragment<wmma::accumulator, 16, 16, 8, float> acc[2][2];
#pragma unroll
    for (int i = 0; i < 2; i++)
#pragma unroll
        for (int j = 0; j < 2; j++) wmma::fill_fragment(acc[i][j], 0.0f);

    for (int kk = 0; kk < K; kk += 32) {
        // Load A tile: 128x32 = 1024 float4, 4 per thread
#pragma unroll
        for (int i = 0; i < 4; i++) {
            int idx = tid + i * 256;
            int r = idx >> 3, k4 = (idx & 7) << 2;
            float4 v = *reinterpret_cast<const float4*>(A + (size_t)(bm + r) * K + kk + k4);
            float4 t = make_float4(to_tf32(v.x), to_tf32(v.y), to_tf32(v.z), to_tf32(v.w));
            *reinterpret_cast<float4*>(&As[r * 40 + k4]) = t;
        }
        // Load B tile: 32x64 = 512 float4, 2 per thread
#pragma unroll
        for (int i = 0; i < 2; i++) {
            int idx = tid + i * 256;
            int r = idx >> 4, c4 = (idx & 15) << 2;
            float4 v = *reinterpret_cast<const float4*>(B + (size_t)(kk + r) * N + bn + c4);
            float4 t = make_float4(to_tf32(v.x), to_tf32(v.y), to_tf32(v.z), to_tf32(v.w));
            *reinterpret_cast<float4*>(&Bs[r * 72 + c4]) = t;
        }
        __syncthreads();

#pragma unroll
        for (int ks = 0; ks < 4; ks++) {
            wmma::fragment<wmma::matrix_a, 16, 16, 8, wmma::precision::tf32, wmma::row_major> a[2];
            wmma::fragment<wmma::matrix_b, 16, 16, 8, wmma::precision::tf32, wmma::row_major> b[2];
#pragma unroll
            for (int i = 0; i < 2; i++)
                wmma::load_matrix_sync(a[i], &As[(wr + i * 16) * 40 + ks * 8], 40);
#pragma unroll
            for (int j = 0; j < 2; j++)
                wmma::load_matrix_sync(b[j], &Bs[(ks * 8) * 72 + wc + j * 16], 72);
#pragma unroll
            for (int i = 0; i < 2; i++)
#pragma unroll
                for (int j = 0; j < 2; j++)
                    wmma::mma_sync(acc[i][j], a[i], b[j], acc[i][j]);
        }
        __syncthreads();
    }

#pragma unroll
    for (int i = 0; i < 2; i++)
#pragma unroll
        for (int j = 0; j < 2; j++)
            wmma::store_matrix_sync(C + (size_t)(bm + wr + i * 16) * N + bn + wc + j * 16,
                                    acc[i][j], N, wmma::mem_row_major);
}

// ---------------------------------------------------------------------------
// RoPE applied in-place to g_q and g_k.
// ---------------------------------------------------------------------------
__global__ void rope_kernel(const float* __restrict__ fcos, const float* __restrict__ fsin)
{
    int idx = blockIdx.x * blockDim.x + threadIdx.x;  // SEQ*NHEAD*64 pairs
    if (idx >= SEQ * NHEAD * (HDIM / 2)) return;
    int i = idx & 63;
    int h = (idx >> 6) & (NHEAD - 1);
    int s = idx >> 11;  // /(64*32)
    float c  = fcos[s * 64 + i];
    float sn = fsin[s * 64 + i];
    size_t off = (size_t)s * DIMSZ + h * HDIM + 2 * i;
    float q0 = g_q[off], q1 = g_q[off + 1];
    g_q[off]     = q0 * c - q1 * sn;
    g_q[off + 1] = q0 * sn + q1 * c;
    float k0 = g_k[off], k1 = g_k[off + 1];
    g_k[off]     = k0 * c - k1 * sn;
    g_k[off + 1] = k0 * sn + k1 * c;
}

// ---------------------------------------------------------------------------
// Flash attention: block = (q-block of 64 rows, head). Online softmax, causal.
// ---------------------------------------------------------------------------
#define LDQ 136   // 128 + 8 pad
#define LDS_S 72  // 64 + 8 pad
#define FLASH_SMEM_FLOATS (4 * 64 * LDQ + 64 * LDS_S + 3 * 64)
#define FLASH_SMEM_BYTES (FLASH_SMEM_FLOATS * 4)

__global__ __launch_bounds__(256) void flash_attn()
{
    extern __shared__ float sm[];
    float* Qs   = sm;                  // 64 x LDQ
    float* Ks   = Qs + 64 * LDQ;       // 64 x LDQ
    float* Vs   = Ks + 64 * LDQ;       // 64 x LDQ
    float* Os   = Vs + 64 * LDQ;       // 64 x LDQ (fp32 accum)
    float* Ss   = Os + 64 * LDQ;       // 64 x LDS_S
    float* mrow = Ss + 64 * LDS_S;
    float* lrow = mrow + 64;
    float* arow = lrow + 64;

    const int qb  = blockIdx.x;
    const int h   = blockIdx.y;
    const int tid = threadIdx.x;
    const int w   = tid >> 5;
    const float scale = 0.08838834764831845f;  // 1/sqrt(128)

    // Load Q tile (64 x 128), convert to tf32
    const float* Qg = g_q + (size_t)qb * 64 * DIMSZ + h * HDIM;
#pragma unroll
    for (int i = 0; i < 8; i++) {
        int idx = tid + i * 256;           // 2048 float4
        int r = idx >> 5, d4 = (idx & 31) << 2;
        float4 v = *reinterpret_cast<const float4*>(Qg + (size_t)r * DIMSZ + d4);
        float4 t = make_float4(to_tf32(v.x), to_tf32(v.y), to_tf32(v.z), to_tf32(v.w));
        *reinterpret_cast<float4*>(&Qs[r * LDQ + d4]) = t;
    }
    for (int i = tid; i < 64 * LDQ; i += 256) Os[i] = 0.0f;
    if (tid < 64) { mrow[tid] = -1e30f; lrow[tid] = 0.0f; }
    __syncthreads();

    for (int kt = 0; kt <= qb; kt++) {
        const float* Kg = g_k + (size_t)kt * 64 * DIMSZ + h * HDIM;
        const float* Vg = g_v + (size_t)kt * 64 * DIMSZ + h * HDIM;
#pragma unroll
        for (int i = 0; i < 8; i++) {
            int idx = tid + i * 256;
            int r = idx >> 5, d4 = (idx & 31) << 2;
            float4 kv = *reinterpret_cast<const float4*>(Kg + (size_t)r * DIMSZ + d4);
            float4 vv = *reinterpret_cast<const float4*>(Vg + (size_t)r * DIMSZ + d4);
            *reinterpret_cast<float4*>(&Ks[r * LDQ + d4]) =
                make_float4(to_tf32(kv.x), to_tf32(kv.y), to_tf32(kv.z), to_tf32(kv.w));
            *reinterpret_cast<float4*>(&Vs[r * LDQ + d4]) =
                make_float4(to_tf32(vv.x), to_tf32(vv.y), to_tf32(vv.z), to_tf32(vv.w));
        }
        __syncthreads();

        // S = scale * Q @ K^T : warp grid 4x2, each warp 16 rows x 32 cols
        {
            const int wr = (w >> 1) * 16;
            const int wc = (w & 1) * 32;
            wmma::fragment<wmma::accumulator, 16, 16, 8, float> c[2];
            wmma::fill_fragment(c[0], 0.0f);
            wmma::fill_fragment(c[1], 0.0f);
#pragma unroll
            for (int ks = 0; ks < 16; ks++) {
                wmma::fragment<wmma::matrix_a, 16, 16, 8, wmma::precision::tf32, wmma::row_major> a;
                wmma::load_matrix_sync(a, &Qs[wr * LDQ + ks * 8], LDQ);
#pragma unroll
                for (int j = 0; j < 2; j++) {
                    wmma::fragment<wmma::matrix_b, 16, 16, 8, wmma::precision::tf32, wmma::col_major> b;
                    wmma::load_matrix_sync(b, &Ks[(wc + j * 16) * LDQ + ks * 8], LDQ);
                    wmma::mma_sync(c[j], a, b, c[j]);
                }
            }
#pragma unroll
            for (int j = 0; j < 2; j++) {
#pragma unroll
                for (int t = 0; t < c[j].num_elements; t++) c[j].x[t] *= scale;
                wmma::store_matrix_sync(&Ss[wr * LDS_S + wc + j * 16], c[j], LDS_S,
                                        wmma::mem_row_major);
            }
        }
        __syncthreads();

        // Online softmax: 4 threads per row, 16 cols each
        {
            int r   = tid >> 2;
            int sub = tid & 3;
            int smax = (kt == qb) ? (r + 1) : 64;  // causal: valid cols
            float mloc = -1e30f;
            int c0 = sub * 16;
#pragma unroll
            for (int c = 0; c < 16; c++) {
                int cc = c0 + c;
                if (cc < smax) mloc = fmaxf(mloc, Ss[r * LDS_S + cc]);
            }
#pragma unroll
            for (int o = 1; o < 4; o <<= 1)
                mloc = fmaxf(mloc, __shfl_xor_sync(0xffffffffu, mloc, o));
            float mo = mrow[r];
            float mn = fmaxf(mo, mloc);
            float alpha = __expf(mo - mn);
            float lsum = 0.0f;
#pragma unroll
            for (int c = 0; c < 16; c++) {
                int cc = c0 + c;
                float p = (cc < smax) ? __expf(Ss[r * LDS_S + cc] - mn) : 0.0f;
                p = to_tf32(p);
                Ss[r * LDS_S + cc] = p;
                lsum += p;
            }
#pragma unroll
            for (int o = 1; o < 4; o <<= 1)
                lsum += __shfl_xor_sync(0xffffffffu, lsum, o);
            if (sub == 0) {
                lrow[r] = lrow[r] * alpha + lsum;
                mrow[r] = mn;
                arow[r] = alpha;
            }
        }
        __syncthreads();

        // Rescale O accumulator
        for (int i = tid; i < 64 * 128; i += 256) {
            int r = i >> 7, d = i & 127;
            Os[r * LDQ + d] *= arow[r];
        }
        __syncthreads();

        // O += P @ V : warp grid 2x4, each warp 32x32
        {
            const int wr = (w >> 2) * 32;
            const int wc = (w & 3) * 32;
            wmma::fragment<wmma::accumulator, 16, 16, 8, float> c[2][2];
#pragma unroll
            for (int i = 0; i < 2; i++)
#pragma unroll
                for (int j = 0; j < 2; j++)
                    wmma::load_matrix_sync(c[i][j], &Os[(wr + i * 16) * LDQ + wc + j * 16],
                                           LDQ, wmma::mem_row_major);
#pragma unroll
            for (int ks = 0; ks < 8; ks++) {
                wmma::fragment<wmma::matrix_a, 16, 16, 8, wmma::precision::tf32, wmma::row_major> a[2];
                wmma::fragment<wmma::matrix_b, 16, 16, 8, wmma::precision::tf32, wmma::row_major> b[2];
#pragma unroll
                for (int i = 0; i < 2; i++)
                    wmma::load_matrix_sync(a[i], &Ss[(wr + i * 16) * LDS_S + ks * 8], LDS_S);
#pragma unroll
                for (int j = 0; j < 2; j++)
                    wmma::load_matrix_sync(b[j], &Vs[(ks * 8) * LDQ + wc + j * 16], LDQ);
#pragma unroll
                for (int i = 0; i < 2; i++)
#pragma unroll
                    for (int j = 0; j < 2; j++)
                        wmma::mma_sync(c[i][j], a[i], b[j], c[i][j]);
            }
#pragma unroll
            for (int i = 0; i < 2; i++)
#pragma unroll
                for (int j = 0; j < 2; j++)
                    wmma::store_matrix_sync(&Os[(wr + i * 16) * LDQ + wc + j * 16],
                                            c[i][j], LDQ, wmma::mem_row_major);
        }
        __syncthreads();
    }

    // Epilogue: divide by row sum, write to scratch O
    float* Og = g_o + (size_t)qb * 64 * DIMSZ + h * HDIM;
    for (int i = tid; i < 64 * 128; i += 256) {
        int r = i >> 7, d = i & 127;
        Og[(size_t)r * DIMSZ + d] = Os[r * LDQ + d] / lrow[r];
    }
}

// ---------------------------------------------------------------------------
extern "C" void kernel_launch(void* const* d_in, const int* in_sizes, int n_in,
                              void* d_out, int out_size)
{
    const float* x  = (const float*)d_in[0];
    const float* wq = (const float*)d_in[1];
    const float* wk = (const float*)d_in[2];
    const float* wv = (const float*)d_in[3];
    const float* wo = (const float*)d_in[4];
    const float* fc = (const float*)d_in[5];
    const float* fs = (const float*)d_in[6];
    // d_in[7] = mask (causal handled analytically), d_in[8] = start_pos (0)
    float* out = (float*)d_out;

    float *q, *k, *v, *o;
    cudaGetSymbolAddress((void**)&q, g_q);
    cudaGetSymbolAddress((void**)&k, g_k);
    cudaGetSymbolAddress((void**)&v, g_v);
    cudaGetSymbolAddress((void**)&o, g_o);

    dim3 ggrid(SEQ / 128, DIMSZ / 64);
    gemm_tf32<<<ggrid, 256>>>(x, wq, q, SEQ, DIMSZ, DIMSZ);
    gemm_tf32<<<ggrid, 256>>>(x, wk, k, SEQ, DIMSZ, DIMSZ);
    gemm_tf32<<<ggrid, 256>>>(x, wv, v, SEQ, DIMSZ, DIMSZ);

    int npairs = SEQ * NHEAD * (HDIM / 2);
    rope_kernel<<<(npairs + 255) / 256, 256>>>(fc, fs);

    cudaFuncSetAttribute(flash_attn, cudaFuncAttributeMaxDynamicSharedMemorySize,
                         FLASH_SMEM_BYTES);
    flash_attn<<<dim3(SEQ / 64, NHEAD), 256, FLASH_SMEM_BYTES>>>();

    gemm_tf32<<<ggrid, 256>>>(o, wo, out, SEQ, DIMSZ, DIMSZ);
}